// round 7
// baseline (speedup 1.0000x reference)
#include <cuda_runtime.h>

#define NB    16
#define NCP   64
#define NTPL  2048
#define HD    10
#define NSTEP 6
#define DTC   0.2f
#define LOG2E 1.4426950408889634f

#define SH_CTAS 8      // CTAs per cluster = per batch
#define SH_THR  256

typedef unsigned long long ull;

// ---- scratch (static device globals; no allocation) ----
__device__ float2 g_P[NSTEP + 1][NB * NCP];
__device__ float2 g_Q[NSTEP + 1][NB * NCP];

// ---------------- packed f32x2 helpers ----------------
__device__ __forceinline__ ull pack2(float lo, float hi) {
    ull d; asm("mov.b64 %0, {%1,%2};" : "=l"(d) : "f"(lo), "f"(hi)); return d;
}
__device__ __forceinline__ void unpack2(ull d, float& lo, float& hi) {
    asm("mov.b64 {%0,%1}, %2;" : "=f"(lo), "=f"(hi) : "l"(d));
}
__device__ __forceinline__ ull fma2(ull a, ull b, ull c) {
    ull d; asm("fma.rn.f32x2 %0, %1, %2, %3;" : "=l"(d) : "l"(a), "l"(b), "l"(c)); return d;
}
__device__ __forceinline__ ull add2(ull a, ull b) {
    ull d; asm("add.rn.f32x2 %0, %1, %2;" : "=l"(d) : "l"(a), "l"(b)); return d;
}
__device__ __forceinline__ float tanhfast(float x) {
    float y; asm("tanh.approx.f32 %0, %1;" : "=f"(y) : "f"(x)); return y;
}
__device__ __forceinline__ float ex2f(float x) {
    float y; asm("ex2.approx.f32 %0, %1;" : "=f"(y) : "f"(x)); return y;
}

// ------------------------------------------------------------------
// MLP forward + 2-tangent JVP (tangent dirs = rows da, db of W1)
// ------------------------------------------------------------------
__device__ __forceinline__ void mlp_jac(
    float z0, float z1, float z2, float z3, int da, int db,
    const float* __restrict__ sW1, const float* __restrict__ sb1,
    const float* __restrict__ sW2, const float* __restrict__ sb2,
    const float* __restrict__ sW3, const float* __restrict__ sb3,
    float o[3], float ja[3], float jb[3]) {
    float h1[HD], ta[HD], tb[HD];
#pragma unroll
    for (int n = 0; n < HD; n++) {
        float u = sb1[n] + z0 * sW1[n] + z1 * sW1[10 + n] + z2 * sW1[20 + n] + z3 * sW1[30 + n];
        float h = tanhfast(u);
        float g = 1.0f - h * h;
        h1[n] = h;
        ta[n] = g * sW1[da * 10 + n];
        tb[n] = g * sW1[db * 10 + n];
    }
    float u2[HD], s2a[HD], s2b[HD];
#pragma unroll
    for (int m = 0; m < HD; m++) { u2[m] = sb2[m]; s2a[m] = 0.f; s2b[m] = 0.f; }
#pragma unroll
    for (int n = 0; n < HD; n++) {
        float h = h1[n], aa = ta[n], bb = tb[n];
#pragma unroll
        for (int m = 0; m < HD; m++) {
            float w = sW2[n * 10 + m];
            u2[m] += h * w;
            s2a[m] += aa * w;
            s2b[m] += bb * w;
        }
    }
#pragma unroll
    for (int c = 0; c < 3; c++) { o[c] = sb3[c]; ja[c] = 0.f; jb[c] = 0.f; }
#pragma unroll
    for (int m = 0; m < HD; m++) {
        float h = tanhfast(u2[m]);
        float g = 1.0f - h * h;
        float aa = s2a[m] * g, bb = s2b[m] * g;
#pragma unroll
        for (int c = 0; c < 3; c++) {
            float w = sW3[m * 3 + c];
            o[c] += h * w;
            ja[c] += aa * w;
            jb[c] += bb * w;
        }
    }
}

// ------------------------------------------------------------------
// all 6 shooting steps: 16 clusters (one per batch) x 8 CTAs x 256 thr.
// barrier.cluster between steps (~400cyc) replaces the global grid barrier.
// Cross-CTA P/Q reads use __ldcg (L2, bypasses possibly-stale L1).
// Thread t: j = t&63, half = (t>>6)&1, asl = t>>7.
// CTA r handles a in [8r, 8r+8); this thread does a = 8r + 4*asl + {0..3}.
// ------------------------------------------------------------------
__global__ void __launch_bounds__(SH_THR, 2) __cluster_dims__(SH_CTAS, 1, 1)
shoot_all(
    const float* __restrict__ q0, const float* __restrict__ cp,
    const float* __restrict__ W1, const float* __restrict__ b1,
    const float* __restrict__ W2, const float* __restrict__ b2,
    const float* __restrict__ W3, const float* __restrict__ b3) {
    __shared__ float sW1[40], sb1[10], sW2[100], sb2[10], sW3[30], sb3[3];
    __shared__ float red[2][4][4][4];   // [asl][a_local][warp_in_group][4 vals]
    int t = threadIdx.x;
    for (int i = t; i < 40; i += SH_THR) sW1[i] = W1[i];
    for (int i = t; i < 100; i += SH_THR) sW2[i] = W2[i];
    for (int i = t; i < 30; i += SH_THR) sW3[i] = W3[i];
    if (t < 10) { sb1[t] = b1[t]; sb2[t] = b2[t]; }
    if (t < 3) sb3[t] = b3[t];
    __syncthreads();

    int b = blockIdx.x >> 3;
    int r = blockIdx.x & 7;
    int j = t & 63, half = (t >> 6) & 1, asl = t >> 7;
    int abase = r * 8 + asl * 4;
    int wgrp = (t >> 5) & 3;   // warp index within the 128-thread (j,half) group
    const float2* cp2 = (const float2*)cp;
    const float2* q02 = (const float2*)q0;

    for (int k = 0; k < NSTEP; k++) {
        float2 pj, qj;
        if (k == 0) { pj = __ldg(&cp2[j]); qj = __ldg(&q02[b * NCP + j]); }
        else        { pj = __ldcg(&g_P[k][b * NCP + j]); qj = __ldcg(&g_Q[k][b * NCP + j]); }

#pragma unroll
        for (int aa = 0; aa < 4; aa++) {
            int a = abase + aa;
            float2 pa, qa;
            if (k == 0) { pa = __ldg(&cp2[a]); qa = __ldg(&q02[b * NCP + a]); }
            else        { pa = __ldcg(&g_P[k][b * NCP + a]); qa = __ldcg(&g_Q[k][b * NCP + a]); }

            // half 0: m(pa,pj) tangents 0,1 ; half 1: m(pj,pa) tangents 2,3
            float z0 = half ? pj.x : pa.x, z1 = half ? pj.y : pa.y;
            float z2 = half ? pa.x : pj.x, z3 = half ? pa.y : pj.y;
            int da = half * 2, db = half * 2 + 1;

            float o[3], ja[3], jb[3];
            mlp_jac(z0, z1, z2, z3, da, db, sW1, sb1, sW2, sb2, sW3, sb3, o, ja, jb);

            float ea = __expf(o[1]), eb = __expf(o[2]);
            float vqx = 0.5f * (ea * qj.x + o[0] * qj.y);
            float vqy = 0.5f * (o[0] * qj.x + eb * qj.y);
            float cw = qa.x * qj.y + qa.y * qj.x;
            float w1 = ea * (qa.x * qj.x), w2 = eb * (qa.y * qj.y);
            float gpx = 0.5f * (cw * ja[0] + w1 * ja[1] + w2 * ja[2]);
            float gpy = 0.5f * (cw * jb[0] + w1 * jb[1] + w2 * jb[2]);

#pragma unroll
            for (int off = 16; off > 0; off >>= 1) {
                vqx += __shfl_down_sync(0xffffffffu, vqx, off);
                vqy += __shfl_down_sync(0xffffffffu, vqy, off);
                gpx += __shfl_down_sync(0xffffffffu, gpx, off);
                gpy += __shfl_down_sync(0xffffffffu, gpy, off);
            }
            if ((t & 31) == 0) {
                red[asl][aa][wgrp][0] = vqx; red[asl][aa][wgrp][1] = vqy;
                red[asl][aa][wgrp][2] = gpx; red[asl][aa][wgrp][3] = gpy;
            }
        }
        __syncthreads();
        // finalizers: threads with (t&127)<4 handle a_local = t&3 of their aslice
        if ((t & 127) < 4) {
            int al = t & 3;
            int a = r * 8 + asl * 4 + al;
            float VX = red[asl][al][0][0] + red[asl][al][1][0] + red[asl][al][2][0] + red[asl][al][3][0];
            float VY = red[asl][al][0][1] + red[asl][al][1][1] + red[asl][al][2][1] + red[asl][al][3][1];
            float GX = red[asl][al][0][2] + red[asl][al][1][2] + red[asl][al][2][2] + red[asl][al][3][2];
            float GY = red[asl][al][0][3] + red[asl][al][1][3] + red[asl][al][2][3] + red[asl][al][3][3];
            float2 pa, qa;
            if (k == 0) { pa = __ldg(&cp2[a]); qa = __ldg(&q02[b * NCP + a]); }
            else        { pa = __ldcg(&g_P[k][b * NCP + a]); qa = __ldcg(&g_Q[k][b * NCP + a]); }
            g_P[k + 1][b * NCP + a] = make_float2(pa.x + DTC * VX, pa.y + DTC * VY);
            g_Q[k + 1][b * NCP + a] = make_float2(qa.x - DTC * GX, qa.y - DTC * GY);
            if (k == 0) {   // materialize step-0 state for the flow kernel
                g_P[0][b * NCP + a] = pa;
                g_Q[0][b * NCP + a] = qa;
            }
            __threadfence();
        }
        if (k < NSTEP - 1) {
            asm volatile("barrier.cluster.arrive.aligned;" ::: "memory");
            asm volatile("barrier.cluster.wait.aligned;" ::: "memory");
        }
    }
}

// ------------------------------------------------------------------
// packed forward MLP: W2 in REGISTERS (hot); layer-3 weights + b2 from
// shared (cold broadcast LDS). W3 cols 1,2 prescaled by log2e -> ex2.
// ------------------------------------------------------------------
__device__ __forceinline__ void mlp2s(
    const ull u1p[5], const ull W2p[50],
    const ull* sb2p, const float* sW3c0, const ull* sW3p12,
    float b3c0, ull b3p12,
    float& o0, ull& o12) {
    ull u2p[5];
#pragma unroll
    for (int i = 0; i < 5; i++) u2p[i] = sb2p[i];
#pragma unroll
    for (int i = 0; i < 5; i++) {
        float lo, hi; unpack2(u1p[i], lo, hi);
        float h0 = tanhfast(lo), h1 = tanhfast(hi);
        ull hp0 = pack2(h0, h0), hp1 = pack2(h1, h1);
        int n0 = (2 * i) * 5, n1 = (2 * i + 1) * 5;
#pragma unroll
        for (int m = 0; m < 5; m++) u2p[m] = fma2(hp0, W2p[n0 + m], u2p[m]);
#pragma unroll
        for (int m = 0; m < 5; m++) u2p[m] = fma2(hp1, W2p[n1 + m], u2p[m]);
    }
    o0 = b3c0; o12 = b3p12;
#pragma unroll
    for (int i = 0; i < 5; i++) {
        float lo, hi; unpack2(u2p[i], lo, hi);
        float h0 = tanhfast(lo), h1 = tanhfast(hi);
        ull hp0 = pack2(h0, h0), hp1 = pack2(h1, h1);
        o12 = fma2(hp0, sW3p12[2 * i], o12);
        o12 = fma2(hp1, sW3p12[2 * i + 1], o12);
        o0 = fmaf(h1, sW3c0[2 * i + 1], fmaf(h0, sW3c0[2 * i], o0));
    }
}

// ------------------------------------------------------------------
// all 7 flow steps in ONE kernel: x in registers across steps.
// 64-thread CTAs (16 points x 4 j-splits); sA/sB interleaved as
// ulonglong2 rows -> 5 LDS.128 per pair instead of 10 LDS.64.
// ------------------------------------------------------------------
__global__ void __launch_bounds__(64, 6) flow_all(
    const float* __restrict__ tpl, float* __restrict__ dout,
    const float* __restrict__ W1, const float* __restrict__ b1,
    const float* __restrict__ W2, const float* __restrict__ b2,
    const float* __restrict__ W3, const float* __restrict__ b3) {
    __shared__ ulonglong2 sAB[NCP][5];  // .x = A_i (b1 + pj.W1[0:2]), .y = B_i (pj.W1[2:4])
    __shared__ ull sQp[NCP];            // packed (0.5*qx, 0.5*qy)
    __shared__ float sW1[40], sb1[10];
    __shared__ float sW3c0[10];  // W3 col 0
    __shared__ ull sW3p12[10];   // W3 cols 1,2 prescaled by log2e
    __shared__ ull sb2p[5];
    int t = threadIdx.x;
    int blk = blockIdx.x;
    int b = blk >> 7;
    int pt0 = (blk & 127) << 4;
    if (t < 40) sW1[t] = W1[t];
    if (t < 10) {
        sb1[t] = b1[t];
        sW3c0[t] = W3[t * 3 + 0];
        sW3p12[t] = pack2(LOG2E * W3[t * 3 + 1], LOG2E * W3[t * 3 + 2]);
    }
    if (t < 5) sb2p[t] = ((const ull*)b2)[t];

    // W2 resident in registers for the whole kernel (hot path)
    const ull* W2v = (const ull*)W2;
    ull W2p[50];
#pragma unroll
    for (int i = 0; i < 50; i++) W2p[i] = __ldg(&W2v[i]);
    float b3c0 = __ldg(&b3[0]);
    ull b3p12 = pack2(LOG2E * __ldg(&b3[1]), LOG2E * __ldg(&b3[2]));

    int lp = t >> 2, quarter = t & 3;
    int i0 = pt0 + lp;
    float2 x = __ldg(&((const float2*)tpl)[i0]);

    for (int k = 0; k <= NSTEP; k++) {
        __syncthreads();   // prior iteration's reads of sAB done
        {
            // all 64 threads fill one cp row each
            float2 p = g_P[k][b * NCP + t];
            float2 q = g_Q[k][b * NCP + t];
#pragma unroll
            for (int i = 0; i < 5; i++) {
                int n0 = 2 * i, n1 = n0 + 1;
                ulonglong2 v;
                v.x = pack2(sb1[n0] + p.x * sW1[n0] + p.y * sW1[10 + n0],
                            sb1[n1] + p.x * sW1[n1] + p.y * sW1[10 + n1]);
                v.y = pack2(p.x * sW1[20 + n0] + p.y * sW1[30 + n0],
                            p.x * sW1[20 + n1] + p.y * sW1[30 + n1]);
                sAB[t][i] = v;
            }
            sQp[t] = pack2(0.5f * q.x, 0.5f * q.y);
        }
        // per-thread layer-1 parts for current x
        ull axp[5], bxp[5];
#pragma unroll
        for (int i = 0; i < 5; i++) {
            int n0 = 2 * i, n1 = n0 + 1;
            axp[i] = pack2(sb1[n0] + x.x * sW1[n0] + x.y * sW1[10 + n0],
                           sb1[n1] + x.x * sW1[n1] + x.y * sW1[10 + n1]);
            bxp[i] = pack2(x.x * sW1[20 + n0] + x.y * sW1[30 + n0],
                           x.x * sW1[20 + n1] + x.y * sW1[30 + n1]);
        }
        __syncthreads();

        float vx = 0.f, vy = 0.f;
#pragma unroll 1
        for (int jj = 0; jj < 16; jj++) {
            int j = (jj << 2) | quarter;
            ull u1[5], u1c[5];
#pragma unroll
            for (int i = 0; i < 5; i++) {
                ulonglong2 v = sAB[j][i];
                u1[i]  = add2(axp[i], v.y);   // m(x, pj)
                u1c[i] = add2(v.x, bxp[i]);   // m(pj, x)
            }
            float a0; ull a12;
            mlp2s(u1, W2p, sb2p, sW3c0, sW3p12, b3c0, b3p12, a0, a12);
            float c0; ull c12;
            mlp2s(u1c, W2p, sb2p, sW3c0, sW3p12, b3c0, b3p12, c0, c12);
            float a1, a2, c1, c2;
            unpack2(a12, a1, a2);
            unpack2(c12, c1, c2);
            float s0 = a0 + c0;
            float qx2, qy2; unpack2(sQp[j], qx2, qy2);
            vx = fmaf(ex2f(a1), qx2, vx);
            vx = fmaf(ex2f(c1), qx2, vx);
            vx = fmaf(s0, qy2, vx);
            vy = fmaf(s0, qx2, vy);
            vy = fmaf(ex2f(a2), qy2, vy);
            vy = fmaf(ex2f(c2), qy2, vy);
        }
        // combine the 4 j-splits (adjacent lanes); sum lands in all 4
        vx += __shfl_xor_sync(0xffffffffu, vx, 1);
        vy += __shfl_xor_sync(0xffffffffu, vy, 1);
        vx += __shfl_xor_sync(0xffffffffu, vx, 2);
        vy += __shfl_xor_sync(0xffffffffu, vy, 2);
        x.x = fmaf(DTC, vx, x.x);
        x.y = fmaf(DTC, vy, x.y);
    }
    if (quarter == 0) ((float2*)dout)[b * NTPL + i0] = x;
}

// ------------------------------------------------------------------
extern "C" void kernel_launch(void* const* d_in, const int* in_sizes, int n_in,
                              void* d_out, int out_size) {
    const float* q0  = (const float*)d_in[0];
    const float* tpl = (const float*)d_in[1];
    const float* cp  = (const float*)d_in[2];
    const float* W1  = (const float*)d_in[3];
    const float* b1  = (const float*)d_in[4];
    const float* W2  = (const float*)d_in[5];
    const float* b2  = (const float*)d_in[6];
    const float* W3  = (const float*)d_in[7];
    const float* b3  = (const float*)d_in[8];
    float* out = (float*)d_out;
    (void)in_sizes; (void)n_in; (void)out_size;

    shoot_all<<<NB * SH_CTAS, SH_THR>>>(q0, cp, W1, b1, W2, b2, W3, b3);
    flow_all<<<NB * (NTPL / 16), 64>>>(tpl, out, W1, b1, W2, b2, W3, b3);
}